// round 14
// baseline (speedup 1.0000x reference)
#include <cuda_runtime.h>
#include <cuda_fp16.h>
#include <cstdint>

// DynamicHybridRouter via mma.sync fp16 3-product split GEMM.
// logits = x[M,2048] @ W^T[2048,64] + b; all-mature -> top-2 softmax scatter,
// any-immature -> softmax(logits/2).
//
// Precision: a = hi + lo/2048, hi = f16_rn(a), lo = f16_rn((a-hi)*2048).
// acc1 += ahi*bhi ; acc2 += ahi*blo + alo*bhi ; logits = acc1 + acc2/2048.
// Dropped lo*lo ~2^-24 rel -> logit err ~2e-7.
//
// R12 (on the best R9b barrier-free skeleton):
//  - k-slot remap: mma slots (2fc,2fc+1,2fc+8,2fc+9) hold physical k
//    (4fc..4fc+3), applied to BOTH A and B -> each lane's A fragment is one
//    contiguous float4 (2x fewer A loads/wavefronts).
//  - warp-wide prefetch.global.L1 of the NEXT tile's 4KB B block (32 lines,
//    one instr, zero regs) -> same-tile bq1 loads become L1 hits.

constexpr int KD = 2048;
constexpr int NEXP = 64;
constexpr int BM = 128;
constexpr int NT = KD / 32;          // 64 k-tiles; 1 k16 step per warp each
constexpr int LGS = 68;
constexpr float TEMP_INV = 0.5f;
constexpr float LO_SCALE = 2048.0f;
constexpr float LO_INV = 1.0f / 2048.0f;

// [k16=128][e=64][fc=4] -> uint4 {hi(k=4fc,4fc+1), hi(4fc+2,4fc+3),
//                                 lo(4fc,4fc+1),   lo(4fc+2,4fc+3)}
// (k-slot remap kappa: fragment slots (2fc,2fc+1)->(4fc,4fc+1),
//  (2fc+8,2fc+9)->(4fc+2,4fc+3); same kappa on A.)
__device__ uint4 g_wpack[128 * 64 * 4];

__device__ __forceinline__ uint32_t h2u(__half2 h) {
    return *reinterpret_cast<uint32_t*>(&h);
}

// split float4 (4 consecutive k) into hi/lo half2 pairs
__device__ __forceinline__ void cvt4(float4 v, uint32_t& h01, uint32_t& h23,
                                     uint32_t& l01, uint32_t& l23) {
    __half2 a = __float22half2_rn(make_float2(v.x, v.y));
    __half2 b = __float22half2_rn(make_float2(v.z, v.w));
    float2 fa = __half22float2(a);
    float2 fb = __half22float2(b);
    __half2 la = __float22half2_rn(
        make_float2((v.x - fa.x) * LO_SCALE, (v.y - fa.y) * LO_SCALE));
    __half2 lb = __float22half2_rn(
        make_float2((v.z - fb.x) * LO_SCALE, (v.w - fb.y) * LO_SCALE));
    h01 = h2u(a); h23 = h2u(b); l01 = h2u(la); l23 = h2u(lb);
}

__global__ void __launch_bounds__(256) pack_w_kernel(const float* __restrict__ gw) {
    int i = blockIdx.x * 256 + threadIdx.x;     // 32768 items
    int fc = i & 3, e = (i >> 2) & 63, k16 = i >> 8;
    float4 v = *(const float4*)(gw + e * KD + k16 * 16 + 4 * fc);
    uint4 q;
    cvt4(v, q.x, q.y, q.z, q.w);
    g_wpack[i] = q;
}

__device__ __forceinline__ void mma16(float* d, const uint32_t* a,
                                      uint32_t b0, uint32_t b1) {
    asm volatile(
        "mma.sync.aligned.m16n8k16.row.col.f32.f16.f16.f32 "
        "{%0,%1,%2,%3}, {%4,%5,%6,%7}, {%8,%9}, {%0,%1,%2,%3};"
        : "+f"(d[0]), "+f"(d[1]), "+f"(d[2]), "+f"(d[3])
        : "r"(a[0]), "r"(a[1]), "r"(a[2]), "r"(a[3]), "r"(b0), "r"(b1));
}

__global__ void __launch_bounds__(512, 1)
router_fp16(const float* __restrict__ x,
            const float* __restrict__ gb,
            const int*   __restrict__ mat,
            float*       __restrict__ out)
{
    __shared__ __align__(16) float lg[BM * LGS + NEXP];
    float* sbias = lg + BM * LGS;

    const int tid = threadIdx.x;
    const int w   = tid >> 5;
    const int l   = tid & 31;
    const int fr  = l >> 2;           // A row-in-group / B n-in-group
    const int fc  = l & 3;            // fragment k quad
    const int ms  = w & 7;            // M slice (16 rows)
    const int kg  = w >> 3;           // k16 half of each 32-k tile
    const int blockRow = blockIdx.x * BM;

    int imm = 0;
    if (tid < NEXP) {
        imm = (mat[tid] == 0) ? 1 : 0;
        sbias[tid] = gb[tid];
    }
    const int anyImm = __syncthreads_or(imm);

    float acc1[8][4], acc2[8][4];
#pragma unroll
    for (int nt = 0; nt < 8; ++nt)
#pragma unroll
        for (int q = 0; q < 4; ++q) { acc1[nt][q] = 0.f; acc2[nt][q] = 0.f; }

    // per-lane A: rows (blockRow + ms*16 + fr) and +8; k = kt*32 + kg*16 + 4fc
    const float* xa = x + (size_t)(blockRow + ms * 16 + fr) * KD + kg * 16 + 4 * fc;

    // A raw stages: [rh] = row fr (+0) / fr+8, one float4 each
    float4 raw0[2], raw1[2];
    raw0[0] = *(const float4*)(xa);
    raw0[1] = *(const float4*)(xa + (size_t)8 * KD);

    const uint4* wbase = g_wpack + (size_t)kg * 256 + fr * 4 + fc;
    const char* pfbase = (const char*)(g_wpack + (size_t)kg * 256) + l * 128;

    // B double buffer: bq0 = current/next tile half0, bq1 = current half1
    uint4 bq0[4], bq1[4];
#pragma unroll
    for (int nt = 0; nt < 4; ++nt) bq0[nt] = __ldg(wbase + nt * 32);

#pragma unroll 2
    for (int kt = 0; kt < NT; ++kt) {
        // ---- L1 prefetch: next tile's entire 4KB B block (32 lines) ----
        if (kt + 1 < NT) {
            const char* pf = pfbase + (size_t)((kt + 1) * 2) * 4096;
            asm volatile("prefetch.global.L1 [%0];" :: "l"(pf));
        }

        // ---- A prefetch for kt+1, issued early (full iteration to land) ----
        if (kt + 1 < NT) {
            const float* xt = xa + (kt + 1) * 32;
            raw1[0] = *(const float4*)(xt);
            raw1[1] = *(const float4*)(xt + (size_t)8 * KD);
        }

        const uint4* wt = wbase + (size_t)(kt * 2) * 256;

        // ---- B load: this tile's half1 (L1-hot via last tile's prefetch) ----
#pragma unroll
        for (int nt = 0; nt < 4; ++nt) bq1[nt] = __ldg(wt + (nt + 4) * 32);

        // ---- A hi/lo fragments: a0/a2 = row fr, a1/a3 = row fr+8 ----
        uint32_t ahi[4], alo[4];
        cvt4(raw0[0], ahi[0], ahi[2], alo[0], alo[2]);
        cvt4(raw0[1], ahi[1], ahi[3], alo[1], alo[3]);

        // ---- half0: experts 0..31 with prefetched bq0 ----
#pragma unroll
        for (int nt = 0; nt < 4; ++nt) mma16(acc1[nt], ahi, bq0[nt].x, bq0[nt].y);
#pragma unroll
        for (int nt = 0; nt < 4; ++nt) mma16(acc2[nt], ahi, bq0[nt].z, bq0[nt].w);
#pragma unroll
        for (int nt = 0; nt < 4; ++nt) mma16(acc2[nt], alo, bq0[nt].x, bq0[nt].y);

        // ---- B load: next tile's half0 (used next iteration) ----
        if (kt + 1 < NT) {
            const uint4* wn = wbase + (size_t)((kt + 1) * 2) * 256;
#pragma unroll
            for (int nt = 0; nt < 4; ++nt) bq0[nt] = __ldg(wn + nt * 32);
        }

        // ---- half1: experts 32..63 with bq1 ----
#pragma unroll
        for (int nt = 0; nt < 4; ++nt) mma16(acc1[nt + 4], ahi, bq1[nt].x, bq1[nt].y);
#pragma unroll
        for (int nt = 0; nt < 4; ++nt) mma16(acc2[nt + 4], ahi, bq1[nt].z, bq1[nt].w);
#pragma unroll
        for (int nt = 0; nt < 4; ++nt) mma16(acc2[nt + 4], alo, bq1[nt].x, bq1[nt].y);

        // rotate A stage
        raw0[0] = raw1[0];
        raw0[1] = raw1[1];
    }

    // ---- k-split reduction into logits SMEM ----
    if (kg == 1) {
#pragma unroll
        for (int nt = 0; nt < 8; ++nt) {
            int row = ms * 16 + fr;
            int e = nt * 8 + fc * 2;
            *(float2*)&lg[row * LGS + e] = make_float2(
                fmaf(acc2[nt][0], LO_INV, acc1[nt][0]),
                fmaf(acc2[nt][1], LO_INV, acc1[nt][1]));
            *(float2*)&lg[(row + 8) * LGS + e] = make_float2(
                fmaf(acc2[nt][2], LO_INV, acc1[nt][2]),
                fmaf(acc2[nt][3], LO_INV, acc1[nt][3]));
        }
    }
    __syncthreads();
    if (kg == 0) {
#pragma unroll
        for (int nt = 0; nt < 8; ++nt) {
            int row = ms * 16 + fr;
            int e = nt * 8 + fc * 2;
            float2 bv = *(const float2*)&sbias[e];
            float2 o0 = *(float2*)&lg[row * LGS + e];
            o0.x += fmaf(acc2[nt][0], LO_INV, acc1[nt][0]) + bv.x;
            o0.y += fmaf(acc2[nt][1], LO_INV, acc1[nt][1]) + bv.y;
            *(float2*)&lg[row * LGS + e] = o0;
            float2 o1 = *(float2*)&lg[(row + 8) * LGS + e];
            o1.x += fmaf(acc2[nt][2], LO_INV, acc1[nt][2]) + bv.x;
            o1.y += fmaf(acc2[nt][3], LO_INV, acc1[nt][3]) + bv.y;
            *(float2*)&lg[(row + 8) * LGS + e] = o1;
        }
    }
    __syncthreads();

    // ---- routing epilogue (identical to the passing kernels) ----
    if (tid < BM) {
        float* lrow = &lg[tid * LGS];
        float* orow = out + (size_t)(blockRow + tid) * NEXP;

        if (!anyImm) {
            float v1 = -3.4e38f, v2 = -3.4e38f;
            int i1 = 0, i2 = 0;
#pragma unroll
            for (int e = 0; e < NEXP; ++e) {
                float v = lrow[e];
                if (v > v1) { v2 = v1; i2 = i1; v1 = v; i1 = e; }
                else if (v > v2) { v2 = v; i2 = e; }
            }
            float t = __expf(v2 - v1);
            float inv = 1.0f / (1.0f + t);
            float4 z = make_float4(0.f, 0.f, 0.f, 0.f);
#pragma unroll
            for (int j = 0; j < NEXP / 4; ++j) ((float4*)orow)[j] = z;
            orow[i1] = inv;
            orow[i2] = t * inv;
        } else {
            float mx = -3.4e38f;
#pragma unroll
            for (int e = 0; e < NEXP; ++e) mx = fmaxf(mx, lrow[e]);
            float sum = 0.f;
#pragma unroll
            for (int e = 0; e < NEXP; ++e) {
                float t = __expf((lrow[e] - mx) * TEMP_INV);
                lrow[e] = t;
                sum += t;
            }
            float inv = 1.0f / sum;
#pragma unroll
            for (int e = 0; e < NEXP; ++e) orow[e] = lrow[e] * inv;
        }
    }
}

extern "C" void kernel_launch(void* const* d_in, const int* in_sizes, int n_in,
                              void* d_out, int out_size) {
    const float* x  = (const float*)d_in[0];
    const float* gw = (const float*)d_in[1];
    const float* gb = (const float*)d_in[2];
    const int*   mt = (const int*)d_in[3];
    float* out = (float*)d_out;

    const int M = in_sizes[0] / KD;     // 16384
    pack_w_kernel<<<128, 256>>>(gw);
    router_fp16<<<M / BM, 512>>>(x, gb, mt, out);
}